// round 2
// baseline (speedup 1.0000x reference)
#include <cuda_runtime.h>
#include <cstdint>

// Problem constants (fixed shapes for this problem)
#define MAX_N 50000
#define MAX_E 800000
#define F_IN  128
#define F_HID 128
#define F_OUT 64

// Scratch (device globals; no allocation allowed in kernel_launch)
__device__ float g_h1 [MAX_N * F_HID];   // layer1 linear output
__device__ float g_agg[MAX_N * F_HID];   // layer1 aggregation buffer
__device__ float g_h3 [MAX_N * F_OUT];   // layer2 linear output
__device__ float g_dinv[MAX_N];
__device__ int   g_deg [MAX_N];

// ---------------------------------------------------------------------------
// degree kernels
// ---------------------------------------------------------------------------
__global__ void k_deg_zero(int n) {
    int i = blockIdx.x * blockDim.x + threadIdx.x;
    if (i < n) g_deg[i] = 0;
}

__global__ void k_deg_count(const int* __restrict__ ei, int E) {
    int e = blockIdx.x * blockDim.x + threadIdx.x;
    if (e < E) atomicAdd(&g_deg[ei[E + e]], 1);   // dst = ei[E + e]
}

__global__ void k_dinv(int n) {
    int i = blockIdx.x * blockDim.x + threadIdx.x;
    if (i < n) g_dinv[i] = rsqrtf((float)g_deg[i] + 1.0f);  // +1 self loop
}

// ---------------------------------------------------------------------------
// Tiled SGEMM: H = A[M,128] @ W[128,BN]; also writes AGG = H * dinv(row)^2
// BM=128, BK=16, TM=8; BN/TN chosen so block = 256 threads.
// grid.x = ceil(M/128), 256 threads.
// ---------------------------------------------------------------------------
template <int BN, int TN>
__global__ void k_gemm_fused(const float* __restrict__ A,
                             const float* __restrict__ W,
                             float* __restrict__ H,
                             float* __restrict__ AGG,
                             const float* __restrict__ dinv,
                             int M) {
    constexpr int BM = 128, BK = 16, TM = 8;
    constexpr int TX = BN / TN;               // threads along N = 16
    static_assert(TX * (BM / TM) == 256, "block must be 256 threads");

    __shared__ float As[BK][BM];              // transposed A tile
    __shared__ float Bs[BK][BN];

    const int tid = threadIdx.x;
    const int ty  = tid / TX;                 // 0..15, row group
    const int tx  = tid % TX;                 // 0..15, col group
    const int row0 = blockIdx.x * BM;

    float acc[TM][TN];
#pragma unroll
    for (int m = 0; m < TM; m++)
#pragma unroll
        for (int n = 0; n < TN; n++) acc[m][n] = 0.0f;

    for (int k0 = 0; k0 < 128; k0 += BK) {
        // Load A tile: 128 rows x 16 cols = 512 float4, 2 per thread
#pragma unroll
        for (int i = 0; i < 2; i++) {
            int l  = tid + i * 256;
            int r  = l >> 2;                  // 0..127
            int c4 = (l & 3) * 4;             // 0,4,8,12
            int grow = row0 + r;
            float4 v = make_float4(0.f, 0.f, 0.f, 0.f);
            if (grow < M)
                v = *(const float4*)(A + (size_t)grow * 128 + k0 + c4);
            As[c4 + 0][r] = v.x;
            As[c4 + 1][r] = v.y;
            As[c4 + 2][r] = v.z;
            As[c4 + 3][r] = v.w;
        }
        // Load W tile: 16 rows x BN cols
        constexpr int BV = BN / 4;            // float4 per W row
        constexpr int NL = (BK * BV) / 256;   // 2 for BN=128, 1 for BN=64
#pragma unroll
        for (int i = 0; i < NL; i++) {
            int l = tid + i * 256;
            int r = l / BV;
            int c = (l % BV) * 4;
            float4 v = *(const float4*)(W + (size_t)(k0 + r) * BN + c);
            *(float4*)(&Bs[r][c]) = v;
        }
        __syncthreads();

#pragma unroll
        for (int k = 0; k < BK; k++) {
            float am[TM], bn[TN];
#pragma unroll
            for (int m = 0; m < TM; m++) am[m] = As[k][ty * TM + m];
#pragma unroll
            for (int n = 0; n < TN; n++) bn[n] = Bs[k][tx * TN + n];
#pragma unroll
            for (int m = 0; m < TM; m++)
#pragma unroll
                for (int n = 0; n < TN; n++)
                    acc[m][n] = fmaf(am[m], bn[n], acc[m][n]);
        }
        __syncthreads();
    }

    // Epilogue: write H and AGG = H * dinv^2 (self-loop term)
#pragma unroll
    for (int m = 0; m < TM; m++) {
        int grow = row0 + ty * TM + m;
        if (grow < M) {
            float d  = dinv[grow];
            float dd = d * d;
#pragma unroll
            for (int n = 0; n < TN; n += 4) {
                float4 v;
                v.x = acc[m][n + 0];
                v.y = acc[m][n + 1];
                v.z = acc[m][n + 2];
                v.w = acc[m][n + 3];
                int col = tx * TN + n;
                *(float4*)(H + (size_t)grow * BN + col) = v;
                float4 w = make_float4(v.x * dd, v.y * dd, v.z * dd, v.w * dd);
                *(float4*)(AGG + (size_t)grow * BN + col) = w;
            }
        }
    }
}

// ---------------------------------------------------------------------------
// Edge scatter: agg[dst] += h[src] * dinv[src]*dinv[dst]
// F/4 lanes per edge, vector float4 RED atomics.
// ---------------------------------------------------------------------------
template <int F>
__global__ void k_scatter(const int* __restrict__ ei,
                          const float* __restrict__ h,
                          float* __restrict__ agg,
                          const float* __restrict__ dinv,
                          int E) {
    constexpr int LPE = F / 4;                // lanes per edge (32 or 16)
    int gt = blockIdx.x * blockDim.x + threadIdx.x;
    int e  = gt / LPE;
    int li = gt % LPE;
    if (e >= E) return;

    int src = __ldg(&ei[e]);
    int dst = __ldg(&ei[E + e]);
    float norm = dinv[src] * dinv[dst];

    float4 v = *(const float4*)(h + (size_t)src * F + li * 4);
    float* p = agg + (size_t)dst * F + li * 4;
    asm volatile("red.global.add.v4.f32 [%0], {%1, %2, %3, %4};"
                 :: "l"(p),
                    "f"(v.x * norm), "f"(v.y * norm),
                    "f"(v.z * norm), "f"(v.w * norm)
                 : "memory");
}

// ---------------------------------------------------------------------------
// out = relu(agg + b), vectorized float4
// ---------------------------------------------------------------------------
template <int F>
__global__ void k_bias_relu(const float* __restrict__ agg,
                            const float* __restrict__ b,
                            float* __restrict__ out,
                            int M) {
    int i = blockIdx.x * blockDim.x + threadIdx.x;    // over M*F/4 float4
    int total = M * (F / 4);
    if (i >= total) return;
    int col4 = (i % (F / 4)) * 4;
    float4 v  = ((const float4*)agg)[i];
    float4 bb = *(const float4*)(b + col4);
    v.x = fmaxf(v.x + bb.x, 0.0f);
    v.y = fmaxf(v.y + bb.y, 0.0f);
    v.z = fmaxf(v.z + bb.z, 0.0f);
    v.w = fmaxf(v.w + bb.w, 0.0f);
    ((float4*)out)[i] = v;
}

// ---------------------------------------------------------------------------
// launch
// ---------------------------------------------------------------------------
extern "C" void kernel_launch(void* const* d_in, const int* in_sizes, int n_in,
                              void* d_out, int out_size) {
    const float* x  = (const float*)d_in[0];
    const int*   ei = (const int*)  d_in[1];
    const float* W1 = (const float*)d_in[2];
    const float* b1 = (const float*)d_in[3];
    const float* W2 = (const float*)d_in[4];
    const float* b2 = (const float*)d_in[5];
    float* out = (float*)d_out;

    const int N = in_sizes[0] / F_IN;
    const int E = in_sizes[1] / 2;

    float *p_h1, *p_agg, *p_h3, *p_dinv;
    cudaGetSymbolAddress((void**)&p_h1,   g_h1);
    cudaGetSymbolAddress((void**)&p_agg,  g_agg);
    cudaGetSymbolAddress((void**)&p_h3,   g_h3);
    cudaGetSymbolAddress((void**)&p_dinv, g_dinv);

    const int T = 256;

    // degrees -> dinv
    k_deg_zero <<<(N + T - 1) / T, T>>>(N);
    k_deg_count<<<(E + T - 1) / T, T>>>(ei, E);
    k_dinv     <<<(N + T - 1) / T, T>>>(N);

    // ---- layer 1 ----
    k_gemm_fused<F_HID, 8><<<(N + 127) / 128, 256>>>(x, W1, p_h1, p_agg, p_dinv, N);
    {
        long long threads = (long long)E * (F_HID / 4);
        k_scatter<F_HID><<<(int)((threads + T - 1) / T), T>>>(ei, p_h1, p_agg, p_dinv, E);
    }
    // relu(agg + b1) -> reuse g_h1 as layer-2 input
    k_bias_relu<F_HID><<<(N * (F_HID / 4) + T - 1) / T, T>>>(p_agg, b1, p_h1, N);

    // ---- layer 2 ----
    k_gemm_fused<F_OUT, 4><<<(N + 127) / 128, 256>>>(p_h1, W2, p_h3, out, p_dinv, N);
    {
        long long threads = (long long)E * (F_OUT / 4);
        k_scatter<F_OUT><<<(int)((threads + T - 1) / T), T>>>(ei, p_h3, out, p_dinv, E);
    }
    k_bias_relu<F_OUT><<<(N * (F_OUT / 4) + T - 1) / T, T>>>(out, b2, out, N);
}